// round 9
// baseline (speedup 1.0000x reference)
#include <cuda_runtime.h>

__device__ __forceinline__ float ex2(float x) {
    float r; asm("ex2.approx.ftz.f32 %0,%1;" : "=f"(r) : "f"(x)); return r;
}

#define LOG2E 1.4426950408889634f

// ---- folded-parameter layout in shared P[256] ----
// [0..32)    G    gate weights [i*8+e]   (log2e-prescaled)
// [32..40)   gb   gate bias              (log2e-prescaled)
// [40..200)  E    per-expert 20: [e*20 + i*4 + j]=EP(4x4), [e*20+16+j]=epb
// [200..216) RP   resid folded thru proj [i*4+j]
// [216..220) rpb
// [220..224) dC   differenced combine    (log2e-prescaled)
// [224]      dcb                         (log2e-prescaled)
// [230..234) pb   proj bias

__device__ double       d_acc[16];   // zero-init at load; last block resets each run
__device__ unsigned int d_count;     // zero-init at load; last block resets each run

__global__ __launch_bounds__(256) void moe_fused_kernel(
    const float4* __restrict__ x4,
    const float* __restrict__ w_embed,  const float* __restrict__ b_embed,
    const float* __restrict__ gate_w,   const float* __restrict__ expert_w,
    const float* __restrict__ expert_b, const float* __restrict__ resid_w,
    const float* __restrict__ resid_b,  const float* __restrict__ comb_w,
    const float* __restrict__ comb_b,   const float* __restrict__ proj_w,
    const float* __restrict__ proj_b,
    float4* __restrict__ o4, float* __restrict__ out, int n, int out_size)
{
    __shared__ alignas(16) float P[256];
    __shared__ alignas(16) float red[8][16];
    // fold staging (block-local, L2-resident source) — ALL 16B-aligned: accessed as float4
    __shared__ alignas(16) float sE[2048];   // expert_w [e*256 + m*16 + k]
    __shared__ alignas(16) float sR[256];    // resid_w  [m*16+k]
    __shared__ alignas(16) float sG[128];    // gate_w   [m*8+e]
    __shared__ alignas(16) float sW[64];     // w_embed  [i*16+m]
    __shared__ alignas(16) float sPj[64];    // proj_w   [k*4+j]
    __shared__ alignas(16) float sEb[128];   // expert_b [e*16+k]
    __shared__ alignas(16) float sBe[16];    // b_embed
    __shared__ alignas(16) float sRb[16];    // resid_b
    __shared__ alignas(16) float sCw[32];    // comb_w   [m*2+c]
    __shared__ unsigned s_last;

    const int t = threadIdx.x;

    // ---------- per-block fold prologue (concurrent across all blocks) ----------
    {
        const float4* s = (const float4*)expert_w;
        float4* d = (float4*)sE;
        d[t] = s[t];
        d[t + 256] = s[t + 256];
    }
    if (t < 64)       ((float4*)sR)[t]        = ((const float4*)resid_w)[t];
    else if (t < 96)  ((float4*)sG)[t - 64]   = ((const float4*)gate_w)[t - 64];
    else if (t < 112) ((float4*)sW)[t - 96]   = ((const float4*)w_embed)[t - 96];
    else if (t < 128) ((float4*)sPj)[t - 112] = ((const float4*)proj_w)[t - 112];
    else if (t < 160) ((float4*)sEb)[t - 128] = ((const float4*)expert_b)[t - 128];
    else if (t < 164) ((float4*)sBe)[t - 160] = ((const float4*)b_embed)[t - 160];
    else if (t < 168) ((float4*)sRb)[t - 164] = ((const float4*)resid_b)[t - 164];
    else if (t < 176) ((float4*)sCw)[t - 168] = ((const float4*)comb_w)[t - 168];
    __syncthreads();

    if (t < 128) {                              // EP[e][i][j]
        int e = t >> 4, i = (t >> 2) & 3, j = t & 3;
        float acc = 0.f;
        #pragma unroll
        for (int k = 0; k < 16; k++) {
            float tmp = 0.f;
            #pragma unroll
            for (int m = 0; m < 16; m++)
                tmp = fmaf(sW[i * 16 + m], sE[e * 256 + m * 16 + k], tmp);
            acc = fmaf(tmp, sPj[k * 4 + j], acc);
        }
        P[40 + e * 20 + i * 4 + j] = acc;
    } else if (t < 160) {                       // epb[e][j]
        int u = t - 128, e = u >> 2, j = u & 3;
        float acc = 0.f;
        #pragma unroll
        for (int k = 0; k < 16; k++) {
            float tmp = sEb[e * 16 + k];
            #pragma unroll
            for (int m = 0; m < 16; m++)
                tmp = fmaf(sBe[m], sE[e * 256 + m * 16 + k], tmp);
            acc = fmaf(tmp, sPj[k * 4 + j], acc);
        }
        P[40 + e * 20 + 16 + j] = acc;
    } else if (t < 176) {                       // RP[i][j]
        int u = t - 160, i = u >> 2, j = u & 3;
        float acc = 0.f;
        #pragma unroll
        for (int k = 0; k < 16; k++) {
            float tmp = 0.f;
            #pragma unroll
            for (int m = 0; m < 16; m++)
                tmp = fmaf(sW[i * 16 + m], sR[m * 16 + k], tmp);
            acc = fmaf(tmp, sPj[k * 4 + j], acc);
        }
        P[200 + i * 4 + j] = acc;
    } else if (t < 180) {                       // rpb[j]
        int j = t - 176;
        float acc = 0.f;
        #pragma unroll
        for (int k = 0; k < 16; k++) {
            float tmp = sRb[k];
            #pragma unroll
            for (int m = 0; m < 16; m++)
                tmp = fmaf(sBe[m], sR[m * 16 + k], tmp);
            acc = fmaf(tmp, sPj[k * 4 + j], acc);
        }
        P[216 + j] = acc;
    } else if (t < 212) {                       // gate W (log2e)
        int u = t - 180, i = u >> 3, e = u & 7;
        float acc = 0.f;
        #pragma unroll
        for (int m = 0; m < 16; m++)
            acc = fmaf(sW[i * 16 + m], sG[m * 8 + e], acc);
        P[i * 8 + e] = acc * LOG2E;
    } else if (t < 220) {                       // gate b (log2e)
        int e = t - 212;
        float acc = 0.f;
        #pragma unroll
        for (int m = 0; m < 16; m++)
            acc = fmaf(sBe[m], sG[m * 8 + e], acc);
        P[32 + e] = acc * LOG2E;
    } else if (t < 224) {                       // dC (log2e)
        int i = t - 220;
        float acc = 0.f;
        #pragma unroll
        for (int m = 0; m < 16; m++)
            acc = fmaf(sW[i * 16 + m], sCw[m * 2 + 1] - sCw[m * 2], acc);
        P[220 + i] = acc * LOG2E;
    } else if (t == 224) {                      // dcb (log2e)
        float acc = comb_b[1] - comb_b[0];
        #pragma unroll
        for (int m = 0; m < 16; m++)
            acc = fmaf(sBe[m], sCw[m * 2 + 1] - sCw[m * 2], acc);
        P[224] = acc * LOG2E;
    } else if (t < 229) {                       // pb
        P[230 + (t - 225)] = proj_b[t - 225];
    }
    __syncthreads();

    // ---------- main streaming loop (R7/R1 proven shape: scalar, shared params) ----------
    float S[8]  = {0.f, 0.f, 0.f, 0.f, 0.f, 0.f, 0.f, 0.f};
    unsigned cnt = 0;     // nibble counters, tokens/thread <= 15

    const int stride = blockDim.x * gridDim.x;
    for (int i = blockIdx.x * blockDim.x + t; i < n; i += stride) {
        const float4 xv = x4[i];

        // gate logits (log2 domain; coeffs prescaled)
        float lg[8];
        #pragma unroll
        for (int e = 0; e < 8; e++)
            lg[e] = fmaf(xv.w, P[24 + e],
                    fmaf(xv.z, P[16 + e],
                    fmaf(xv.y, P[ 8 + e],
                    fmaf(xv.x, P[ 0 + e], P[32 + e]))));

        // first-max argmax (matches jnp.argmax; positive scaling preserves order)
        float m = lg[0]; int idx = 0;
        #pragma unroll
        for (int e = 1; e < 8; e++)
            if (lg[e] > m) { m = lg[e]; idx = e; }

        // softmax probs via raw ex2
        float p[8], sum = 0.f;
        #pragma unroll
        for (int e = 0; e < 8; e++) { p[e] = ex2(lg[e] - m); sum += p[e]; }
        const float inv = __fdividef(1.f, sum);   // == gates[idx]
        #pragma unroll
        for (int e = 0; e < 8; e++) S[e] = fmaf(p[e], inv, S[e]);
        cnt += 1u << (idx << 2);

        // 2-way combine softmax == sigmoid of differenced form (log2 domain)
        const float dl = fmaf(xv.w, P[223], fmaf(xv.z, P[222],
                         fmaf(xv.y, P[221], fmaf(xv.x, P[220], P[224]))));
        const float cw0 = __fdividef(1.f, 1.f + ex2(dl));
        const float cw1 = 1.f - cw0;
        const float a   = cw0 * inv;

        // expert (stride-20 shared block) + residual, both pre-folded thru proj
        const int eo = 40 + idx * 20;
        float4 o;
        float* op = (float*)&o;
        #pragma unroll
        for (int j = 0; j < 4; j++) {
            float ev = fmaf(xv.w, P[eo + 12 + j],
                       fmaf(xv.z, P[eo +  8 + j],
                       fmaf(xv.y, P[eo +  4 + j],
                       fmaf(xv.x, P[eo +      j], P[eo + 16 + j]))));
            float rv = fmaf(xv.w, P[212 + j],
                       fmaf(xv.z, P[208 + j],
                       fmaf(xv.y, P[204 + j],
                       fmaf(xv.x, P[200 + j], P[216 + j]))));
            op[j] = fmaf(a, ev, fmaf(cw1, rv, P[230 + j]));
        }
        o4[i] = o;
    }

    // ---------- aux reduction: warp -> block -> global double atomics ----------
    float Cf[8];
    #pragma unroll
    for (int e = 0; e < 8; e++) Cf[e] = (float)((cnt >> (e << 2)) & 0xFu);

    #pragma unroll
    for (int e = 0; e < 8; e++) {
        #pragma unroll
        for (int off = 16; off; off >>= 1) {
            S[e]  += __shfl_down_sync(0xffffffffu, S[e],  off);
            Cf[e] += __shfl_down_sync(0xffffffffu, Cf[e], off);
        }
    }
    const int lane = t & 31, w = t >> 5;
    if (lane == 0) {
        #pragma unroll
        for (int e = 0; e < 8; e++) { red[w][e] = S[e]; red[w][8 + e] = Cf[e]; }
    }
    __syncthreads();
    if (t < 16) {
        float v = 0.f;
        #pragma unroll
        for (int w2 = 0; w2 < 8; w2++) v += red[w2][t];
        atomicAdd(&d_acc[t], (double)v);
        __threadfence();
    }
    __syncthreads();

    // ---------- last-block finalize (graph-replay-safe reset; proven R2/R3/R5) ----------
    if (t == 0) {
        unsigned old = atomicAdd(&d_count, 1u);
        s_last = (old == gridDim.x - 1) ? 1u : 0u;
    }
    __syncthreads();
    if (s_last && t == 0) {
        volatile double* acc = d_acc;
        double s = 0.0;
        #pragma unroll
        for (int e = 0; e < 8; e++) s += acc[e] * acc[8 + e];
        if (out_size > n * 4) {
            const double dn = (double)n;
            out[n * 4] = (float)(8.0 * s / (dn * dn));
        }
        #pragma unroll
        for (int k = 0; k < 16; k++) acc[k] = 0.0;
        __threadfence();
        d_count = 0u;
    }
}

extern "C" void kernel_launch(void* const* d_in, const int* in_sizes, int n_in,
                              void* d_out, int out_size)
{
    const float* x        = (const float*)d_in[0];
    const float* w_embed  = (const float*)d_in[1];
    const float* b_embed  = (const float*)d_in[2];
    const float* gate_w   = (const float*)d_in[3];
    const float* expert_w = (const float*)d_in[4];
    const float* expert_b = (const float*)d_in[5];
    const float* resid_w  = (const float*)d_in[6];
    const float* resid_b  = (const float*)d_in[7];
    const float* comb_w   = (const float*)d_in[8];
    const float* comb_b   = (const float*)d_in[9];
    const float* proj_w   = (const float*)d_in[10];
    const float* proj_b   = (const float*)d_in[11];

    const int n = in_sizes[0] / 4;          // tokens

    // 8 tokens/thread (nibble-safe <= 15)
    int grid = (n + 256 * 8 - 1) / (256 * 8);
    int min_grid = (n + 256 * 15 - 1) / (256 * 15);
    if (grid < min_grid) grid = min_grid;
    if (grid < 1) grid = 1;

    moe_fused_kernel<<<grid, 256>>>(
        (const float4*)x, w_embed, b_embed, gate_w, expert_w, expert_b,
        resid_w, resid_b, comb_w, comb_b, proj_w, proj_b,
        (float4*)d_out, (float*)d_out, n, out_size);
}

// round 10
// speedup vs baseline: 1.0514x; 1.0514x over previous
#include <cuda_runtime.h>

__device__ __forceinline__ float ex2(float x) {
    float r; asm("ex2.approx.ftz.f32 %0,%1;" : "=f"(r) : "f"(x)); return r;
}

#define LOG2E 1.4426950408889634f

// ---- folded-parameter layout in d_P / P[256] ----
// [0..32)    G    gate weights [i*8+e]   (log2e-prescaled)
// [32..40)   gb   gate bias              (log2e-prescaled)
// [40..200)  E    per-expert 20: [e*20 + i*4 + j]=EP(4x4), [e*20+16+j]=epb
// [200..216) RP   resid folded thru proj [i*4+j]
// [216..220) rpb
// [220..224) dC   differenced combine    (log2e-prescaled)
// [224]      dcb                         (log2e-prescaled)
// [230..234) pb   proj bias
__device__ alignas(16) float d_P[256];
__device__ double           d_acc[16];   // [0..8) prob sums, [8..16) argmax counts

// ================= setup: WARP-PARALLEL folds (48 warps over 6 blocks) =================
// Each 4x4 projected fold output row is computed by one warp: lanes split the
// 256-term (m,k) sum (8 FMA/lane), then 4 shuffle-tree reductions. Depth ~15 ops.
__global__ __launch_bounds__(256) void setup_kernel(
    const float* __restrict__ w_embed,  const float* __restrict__ b_embed,
    const float* __restrict__ gate_w,   const float* __restrict__ expert_w,
    const float* __restrict__ expert_b, const float* __restrict__ resid_w,
    const float* __restrict__ resid_b,  const float* __restrict__ comb_w,
    const float* __restrict__ comb_b,   const float* __restrict__ proj_w,
    const float* __restrict__ proj_b)
{
    const int t    = threadIdx.x;
    const int lane = t & 31;
    const int w    = blockIdx.x * 8 + (t >> 5);   // global warp id, 0..47

    const int k    = lane & 15;     // proj-row index handled by this lane
    const int half = lane >> 4;     // which 8 m-values this lane sums
    const int m0   = half * 8;

    if (w < 32) {
        // EP[e][i][j] = sum_k (sum_m W[i,m] E[e,m,k]) Pj[k,j]
        const int e = w >> 2, i = w & 3;
        float T = 0.f;
        #pragma unroll
        for (int mm = 0; mm < 8; mm++) {
            int m = m0 + mm;
            T = fmaf(w_embed[i * 16 + m], expert_w[(e * 16 + m) * 16 + k], T);
        }
        float acc[4];
        #pragma unroll
        for (int j = 0; j < 4; j++) acc[j] = T * proj_w[k * 4 + j];
        #pragma unroll
        for (int j = 0; j < 4; j++) {
            #pragma unroll
            for (int off = 16; off; off >>= 1)
                acc[j] += __shfl_down_sync(0xffffffffu, acc[j], off);
        }
        if (lane == 0) {
            #pragma unroll
            for (int j = 0; j < 4; j++) d_P[40 + e * 20 + i * 4 + j] = acc[j];
        }
    } else if (w < 40) {
        // epb[e][j] = sum_k (Eb[e,k] + sum_m Be[m] E[e,m,k]) Pj[k,j]
        const int e = w - 32;
        float T = (half == 0) ? expert_b[e * 16 + k] : 0.f;
        #pragma unroll
        for (int mm = 0; mm < 8; mm++) {
            int m = m0 + mm;
            T = fmaf(b_embed[m], expert_w[(e * 16 + m) * 16 + k], T);
        }
        float acc[4];
        #pragma unroll
        for (int j = 0; j < 4; j++) acc[j] = T * proj_w[k * 4 + j];
        #pragma unroll
        for (int j = 0; j < 4; j++) {
            #pragma unroll
            for (int off = 16; off; off >>= 1)
                acc[j] += __shfl_down_sync(0xffffffffu, acc[j], off);
        }
        if (lane == 0) {
            #pragma unroll
            for (int j = 0; j < 4; j++) d_P[40 + e * 20 + 16 + j] = acc[j];
        }
    } else if (w < 44) {
        // RP[i][j] = sum_k (sum_m W[i,m] R[m,k]) Pj[k,j]
        const int i = w - 40;
        float T = 0.f;
        #pragma unroll
        for (int mm = 0; mm < 8; mm++) {
            int m = m0 + mm;
            T = fmaf(w_embed[i * 16 + m], resid_w[m * 16 + k], T);
        }
        float acc[4];
        #pragma unroll
        for (int j = 0; j < 4; j++) acc[j] = T * proj_w[k * 4 + j];
        #pragma unroll
        for (int j = 0; j < 4; j++) {
            #pragma unroll
            for (int off = 16; off; off >>= 1)
                acc[j] += __shfl_down_sync(0xffffffffu, acc[j], off);
        }
        if (lane == 0) {
            #pragma unroll
            for (int j = 0; j < 4; j++) d_P[200 + i * 4 + j] = acc[j];
        }
    } else if (w == 44) {
        // rpb[j] = sum_k (Rb[k] + sum_m Be[m] R[m,k]) Pj[k,j]
        float T = (half == 0) ? resid_b[k] : 0.f;
        #pragma unroll
        for (int mm = 0; mm < 8; mm++) {
            int m = m0 + mm;
            T = fmaf(b_embed[m], resid_w[m * 16 + k], T);
        }
        float acc[4];
        #pragma unroll
        for (int j = 0; j < 4; j++) acc[j] = T * proj_w[k * 4 + j];
        #pragma unroll
        for (int j = 0; j < 4; j++) {
            #pragma unroll
            for (int off = 16; off; off >>= 1)
                acc[j] += __shfl_down_sync(0xffffffffu, acc[j], off);
        }
        if (lane == 0) {
            #pragma unroll
            for (int j = 0; j < 4; j++) d_P[216 + j] = acc[j];
        }
    } else if (w == 45) {
        // gate weights: 32 outputs, one per lane (16-FMA chain, LDG pipelined)
        const int i = lane >> 3, e = lane & 7;
        float acc = 0.f;
        #pragma unroll
        for (int m = 0; m < 16; m++)
            acc = fmaf(w_embed[i * 16 + m], gate_w[m * 8 + e], acc);
        d_P[i * 8 + e] = acc * LOG2E;
    } else if (w == 46) {
        if (lane < 8) {                    // gate bias
            const int e = lane;
            float acc = 0.f;
            #pragma unroll
            for (int m = 0; m < 16; m++)
                acc = fmaf(b_embed[m], gate_w[m * 8 + e], acc);
            d_P[32 + e] = acc * LOG2E;
        } else if (lane < 12) {            // dC
            const int i = lane - 8;
            float acc = 0.f;
            #pragma unroll
            for (int m = 0; m < 16; m++)
                acc = fmaf(w_embed[i * 16 + m], comb_w[m * 2 + 1] - comb_w[m * 2], acc);
            d_P[220 + i] = acc * LOG2E;
        } else if (lane == 12) {           // dcb
            float acc = comb_b[1] - comb_b[0];
            #pragma unroll
            for (int m = 0; m < 16; m++)
                acc = fmaf(b_embed[m], comb_w[m * 2 + 1] - comb_w[m * 2], acc);
            d_P[224] = acc * LOG2E;
        } else if (lane < 17) {            // pb
            d_P[230 + (lane - 13)] = proj_b[lane - 13];
        }
    } else {  // w == 47: zero accumulators (graph-replay-safe)
        if (lane < 16) d_acc[lane] = 0.0;
    }
}

// ================= main: R7's proven loop, byte-for-byte =================
__global__ __launch_bounds__(256) void moe_main_kernel(
    const float4* __restrict__ x4, float4* __restrict__ o4, int n)
{
    __shared__ alignas(16) float P[256];
    __shared__ float red[8][16];

    const int t = threadIdx.x;
    if (t < 64) ((float4*)P)[t] = ((const float4*)d_P)[t];
    __syncthreads();

    float S[8]  = {0.f, 0.f, 0.f, 0.f, 0.f, 0.f, 0.f, 0.f};
    unsigned cnt = 0;     // nibble counters, tokens/thread <= 15

    const int stride = blockDim.x * gridDim.x;
    for (int i = blockIdx.x * blockDim.x + t; i < n; i += stride) {
        const float4 xv = x4[i];

        // gate logits (log2 domain; coeffs prescaled)
        float lg[8];
        #pragma unroll
        for (int e = 0; e < 8; e++)
            lg[e] = fmaf(xv.w, P[24 + e],
                    fmaf(xv.z, P[16 + e],
                    fmaf(xv.y, P[ 8 + e],
                    fmaf(xv.x, P[ 0 + e], P[32 + e]))));

        // first-max argmax (matches jnp.argmax; positive scaling preserves order)
        float m = lg[0]; int idx = 0;
        #pragma unroll
        for (int e = 1; e < 8; e++)
            if (lg[e] > m) { m = lg[e]; idx = e; }

        // softmax probs via raw ex2
        float p[8], sum = 0.f;
        #pragma unroll
        for (int e = 0; e < 8; e++) { p[e] = ex2(lg[e] - m); sum += p[e]; }
        const float inv = __fdividef(1.f, sum);   // == gates[idx]
        #pragma unroll
        for (int e = 0; e < 8; e++) S[e] = fmaf(p[e], inv, S[e]);
        cnt += 1u << (idx << 2);

        // 2-way combine softmax == sigmoid of differenced form (log2 domain)
        const float dl = fmaf(xv.w, P[223], fmaf(xv.z, P[222],
                         fmaf(xv.y, P[221], fmaf(xv.x, P[220], P[224]))));
        const float cw0 = __fdividef(1.f, 1.f + ex2(dl));
        const float cw1 = 1.f - cw0;
        const float a   = cw0 * inv;

        // expert (stride-20 shared block) + residual, both pre-folded thru proj
        const int eo = 40 + idx * 20;
        float4 o;
        float* op = (float*)&o;
        #pragma unroll
        for (int j = 0; j < 4; j++) {
            float ev = fmaf(xv.w, P[eo + 12 + j],
                       fmaf(xv.z, P[eo +  8 + j],
                       fmaf(xv.y, P[eo +  4 + j],
                       fmaf(xv.x, P[eo +      j], P[eo + 16 + j]))));
            float rv = fmaf(xv.w, P[212 + j],
                       fmaf(xv.z, P[208 + j],
                       fmaf(xv.y, P[204 + j],
                       fmaf(xv.x, P[200 + j], P[216 + j]))));
            op[j] = fmaf(a, ev, fmaf(cw1, rv, P[230 + j]));
        }
        o4[i] = o;
    }

    // ---- aux reduction: warp -> block -> global double atomics ----
    float Cf[8];
    #pragma unroll
    for (int e = 0; e < 8; e++) Cf[e] = (float)((cnt >> (e << 2)) & 0xFu);

    #pragma unroll
    for (int e = 0; e < 8; e++) {
        #pragma unroll
        for (int off = 16; off; off >>= 1) {
            S[e]  += __shfl_down_sync(0xffffffffu, S[e],  off);
            Cf[e] += __shfl_down_sync(0xffffffffu, Cf[e], off);
        }
    }
    const int lane = t & 31, w = t >> 5;
    if (lane == 0) {
        #pragma unroll
        for (int e = 0; e < 8; e++) { red[w][e] = S[e]; red[w][8 + e] = Cf[e]; }
    }
    __syncthreads();
    if (t < 16) {
        float v = 0.f;
        #pragma unroll
        for (int w2 = 0; w2 < 8; w2++) v += red[w2][t];
        atomicAdd(&d_acc[t], (double)v);
    }
}

// ================= finalize (tiny kernel) =================
__global__ void finalize_kernel(float* __restrict__ out, int n, int out_size)
{
    if (threadIdx.x == 0 && out_size > n * 4) {
        double s = 0.0;
        #pragma unroll
        for (int e = 0; e < 8; e++) s += d_acc[e] * d_acc[8 + e];
        const double dn = (double)n;
        out[n * 4] = (float)(8.0 * s / (dn * dn));
    }
}

extern "C" void kernel_launch(void* const* d_in, const int* in_sizes, int n_in,
                              void* d_out, int out_size)
{
    const float* x        = (const float*)d_in[0];
    const float* w_embed  = (const float*)d_in[1];
    const float* b_embed  = (const float*)d_in[2];
    const float* gate_w   = (const float*)d_in[3];
    const float* expert_w = (const float*)d_in[4];
    const float* expert_b = (const float*)d_in[5];
    const float* resid_w  = (const float*)d_in[6];
    const float* resid_b  = (const float*)d_in[7];
    const float* comb_w   = (const float*)d_in[8];
    const float* comb_b   = (const float*)d_in[9];
    const float* proj_w   = (const float*)d_in[10];
    const float* proj_b   = (const float*)d_in[11];

    const int n = in_sizes[0] / 4;          // tokens

    setup_kernel<<<6, 256>>>(w_embed, b_embed, gate_w, expert_w, expert_b,
                             resid_w, resid_b, comb_w, comb_b, proj_w, proj_b);

    // 8 tokens/thread (nibble-safe <= 15)
    int grid = (n + 256 * 8 - 1) / (256 * 8);
    int min_grid = (n + 256 * 15 - 1) / (256 * 15);
    if (grid < min_grid) grid = min_grid;
    if (grid < 1) grid = 1;

    moe_main_kernel<<<grid, 256>>>((const float4*)x, (float4*)d_out, n);

    finalize_kernel<<<1, 32>>>((float*)d_out, n, out_size);
}